// round 1
// baseline (speedup 1.0000x reference)
#include <cuda_runtime.h>

// TAHE: masked cosine-similarity weighted pooling.
// out[b,d] = sum_l [ts[b,l]>0] * (dot(cur_n[b], rec_n[b,l]) + 1)/2 * emb[b,l,d]
//
// Inputs (metadata order):
//   d_in[0] recentTimeRepresentations  [B,L,D] f32
//   d_in[1] curTimeRepresentation      [B,D]   f32
//   d_in[2] recentTimestamps           [B,L]   i32
//   d_in[3] recentItemEmbeddings       [B,L,D] f32
// Output: [B,D] f32

#define TAHE_B 4096
#define TAHE_L 200
#define TAHE_D 128
#define WARPS_PER_CTA 8

__global__ __launch_bounds__(WARPS_PER_CTA * 32, 4)
void tahe_kernel(const float* __restrict__ rec,
                 const float* __restrict__ cur,
                 const int*   __restrict__ ts,
                 const float* __restrict__ emb,
                 float*       __restrict__ out) {
    const int warp = threadIdx.x >> 5;
    const int lane = threadIdx.x & 31;
    const int b    = blockIdx.x * WARPS_PER_CTA + warp;
    if (b >= TAHE_B) return;

    // ---- normalize current representation (lane owns 4 contiguous floats) ----
    float4 c = reinterpret_cast<const float4*>(cur + (size_t)b * TAHE_D)[lane];
    float csq = c.x * c.x + c.y * c.y + c.z * c.z + c.w * c.w;
    #pragma unroll
    for (int o = 16; o > 0; o >>= 1)
        csq += __shfl_xor_sync(0xFFFFFFFFu, csq, o);
    const float cinv = rsqrtf(fmaxf(csq, 1e-12f));
    c.x *= cinv; c.y *= cinv; c.z *= cinv; c.w *= cinv;

    const float4* recb = reinterpret_cast<const float4*>(rec + (size_t)b * TAHE_L * TAHE_D);
    const float4* embb = reinterpret_cast<const float4*>(emb + (size_t)b * TAHE_L * TAHE_D);
    const int*    tsb  = ts + (size_t)b * TAHE_L;

    float4 acc = make_float4(0.f, 0.f, 0.f, 0.f);

    // ---- iterate history; whole-warp skip of masked rows (halves DRAM traffic) ----
    for (int l0 = 0; l0 < TAHE_L; l0 += 32) {
        const int li = l0 + lane;
        const int t  = (li < TAHE_L) ? tsb[li] : 0;
        unsigned ballot = __ballot_sync(0xFFFFFFFFu, t > 0);

        while (ballot) {
            const int j = __ffs(ballot) - 1;
            ballot &= ballot - 1;
            const int l = l0 + j;

            // 512B coalesced loads per row
            const float4 r = recb[(size_t)l * 32 + lane];
            const float4 e = embb[(size_t)l * 32 + lane];

            float dsum = r.x * c.x + r.y * c.y + r.z * c.z + r.w * c.w;
            float ssum = r.x * r.x + r.y * r.y + r.z * r.z + r.w * r.w;
            #pragma unroll
            for (int o = 16; o > 0; o >>= 1) {
                dsum += __shfl_xor_sync(0xFFFFFFFFu, dsum, o);
                ssum += __shfl_xor_sync(0xFFFFFFFFu, ssum, o);
            }

            const float sim = dsum * rsqrtf(fmaxf(ssum, 1e-12f));
            const float w   = (sim + 1.0f) * 0.5f;

            acc.x = fmaf(w, e.x, acc.x);
            acc.y = fmaf(w, e.y, acc.y);
            acc.z = fmaf(w, e.z, acc.z);
            acc.w = fmaf(w, e.w, acc.w);
        }
    }

    reinterpret_cast<float4*>(out + (size_t)b * TAHE_D)[lane] = acc;
}

extern "C" void kernel_launch(void* const* d_in, const int* in_sizes, int n_in,
                              void* d_out, int out_size) {
    const float* rec = (const float*)d_in[0];
    const float* cur = (const float*)d_in[1];
    const int*   ts  = (const int*)  d_in[2];
    const float* emb = (const float*)d_in[3];
    float*       out = (float*)d_out;

    const int ctas = TAHE_B / WARPS_PER_CTA;  // 512
    tahe_kernel<<<ctas, WARPS_PER_CTA * 32>>>(rec, cur, ts, emb, out);
}

// round 3
// speedup vs baseline: 1.2138x; 1.2138x over previous
#include <cuda_runtime.h>

// TAHE: masked cosine-similarity weighted pooling.
// out[b,d] = sum_l [ts[b,l]>0] * (dot(cur_n[b], rec_n[b,l]) + 1)/2 * emb[b,l,d]
//
// R2 (retry after infra failure): split L=200 across 2 warps per batch row
// (1024 CTAs -> ~2x occupancy), compact active l-indices into smem,
// process 2 rows/iter for memory-level parallelism.

#define TAHE_B 4096
#define TAHE_L 200
#define TAHE_D 128
#define WARPS_PER_CTA 8
#define ROWS_PER_CTA  4        // batch rows per CTA (2 warps each)
#define L_HALF        100      // L per warp

__global__ __launch_bounds__(WARPS_PER_CTA * 32)
void tahe_kernel(const float* __restrict__ rec,
                 const float* __restrict__ cur,
                 const int*   __restrict__ ts,
                 const float* __restrict__ emb,
                 float*       __restrict__ out) {
    __shared__ short s_list[WARPS_PER_CTA][L_HALF + 8];
    __shared__ float s_part[ROWS_PER_CTA][TAHE_D];   // partials from half==1 warps

    const int warp = threadIdx.x >> 5;
    const int lane = threadIdx.x & 31;
    const int row  = warp >> 1;              // 0..3 within CTA
    const int half = warp & 1;               // which L half
    const int b    = blockIdx.x * ROWS_PER_CTA + row;

    const unsigned lanemask_lt = (1u << lane) - 1u;

    // ---- normalize current representation (lane owns 4 contiguous floats) ----
    float4 c = reinterpret_cast<const float4*>(cur + (size_t)b * TAHE_D)[lane];
    float csq = c.x * c.x + c.y * c.y + c.z * c.z + c.w * c.w;
    #pragma unroll
    for (int o = 16; o > 0; o >>= 1)
        csq += __shfl_xor_sync(0xFFFFFFFFu, csq, o);
    const float cinv = rsqrtf(fmaxf(csq, 1e-12f));
    c.x *= cinv; c.y *= cinv; c.z *= cinv; c.w *= cinv;

    // ---- compact active l indices for this warp's L-half into smem ----
    const int* tsb = ts + (size_t)b * TAHE_L + half * L_HALF;
    int cnt = 0;
    #pragma unroll
    for (int chunk = 0; chunk < 4; chunk++) {           // 4*32 = 128 >= 100
        const int li = chunk * 32 + lane;
        const int t  = (li < L_HALF) ? tsb[li] : 0;
        const unsigned ballot = __ballot_sync(0xFFFFFFFFu, t > 0);
        if (t > 0)
            s_list[warp][cnt + __popc(ballot & lanemask_lt)] =
                (short)(half * L_HALF + li);
        cnt += __popc(ballot);
    }
    __syncwarp();

    const float4* recb = reinterpret_cast<const float4*>(rec + (size_t)b * TAHE_L * TAHE_D);
    const float4* embb = reinterpret_cast<const float4*>(emb + (size_t)b * TAHE_L * TAHE_D);

    float4 acc = make_float4(0.f, 0.f, 0.f, 0.f);

    // ---- main loop: 2 active rows per iteration, independent chains ----
    int i = 0;
    for (; i + 2 <= cnt; i += 2) {
        const int la = s_list[warp][i];
        const int lb = s_list[warp][i + 1];

        const float4 r0 = recb[(size_t)la * 32 + lane];
        const float4 e0 = embb[(size_t)la * 32 + lane];
        const float4 r1 = recb[(size_t)lb * 32 + lane];
        const float4 e1 = embb[(size_t)lb * 32 + lane];

        float d0 = r0.x * c.x + r0.y * c.y + r0.z * c.z + r0.w * c.w;
        float s0 = r0.x * r0.x + r0.y * r0.y + r0.z * r0.z + r0.w * r0.w;
        float d1 = r1.x * c.x + r1.y * c.y + r1.z * c.z + r1.w * c.w;
        float s1 = r1.x * r1.x + r1.y * r1.y + r1.z * r1.z + r1.w * r1.w;
        #pragma unroll
        for (int o = 16; o > 0; o >>= 1) {
            d0 += __shfl_xor_sync(0xFFFFFFFFu, d0, o);
            s0 += __shfl_xor_sync(0xFFFFFFFFu, s0, o);
            d1 += __shfl_xor_sync(0xFFFFFFFFu, d1, o);
            s1 += __shfl_xor_sync(0xFFFFFFFFu, s1, o);
        }

        const float w0 = (d0 * rsqrtf(fmaxf(s0, 1e-12f)) + 1.0f) * 0.5f;
        const float w1 = (d1 * rsqrtf(fmaxf(s1, 1e-12f)) + 1.0f) * 0.5f;

        acc.x = fmaf(w0, e0.x, fmaf(w1, e1.x, acc.x));
        acc.y = fmaf(w0, e0.y, fmaf(w1, e1.y, acc.y));
        acc.z = fmaf(w0, e0.z, fmaf(w1, e1.z, acc.z));
        acc.w = fmaf(w0, e0.w, fmaf(w1, e1.w, acc.w));
    }
    if (i < cnt) {   // odd tail
        const int la = s_list[warp][i];
        const float4 r0 = recb[(size_t)la * 32 + lane];
        const float4 e0 = embb[(size_t)la * 32 + lane];
        float d0 = r0.x * c.x + r0.y * c.y + r0.z * c.z + r0.w * c.w;
        float s0 = r0.x * r0.x + r0.y * r0.y + r0.z * r0.z + r0.w * r0.w;
        #pragma unroll
        for (int o = 16; o > 0; o >>= 1) {
            d0 += __shfl_xor_sync(0xFFFFFFFFu, d0, o);
            s0 += __shfl_xor_sync(0xFFFFFFFFu, s0, o);
        }
        const float w0 = (d0 * rsqrtf(fmaxf(s0, 1e-12f)) + 1.0f) * 0.5f;
        acc.x = fmaf(w0, e0.x, acc.x);
        acc.y = fmaf(w0, e0.y, acc.y);
        acc.z = fmaf(w0, e0.z, acc.z);
        acc.w = fmaf(w0, e0.w, acc.w);
    }

    // ---- combine the two half-warps ----
    if (half == 1)
        reinterpret_cast<float4*>(s_part[row])[lane] = acc;
    __syncthreads();
    if (half == 0) {
        const float4 p = reinterpret_cast<const float4*>(s_part[row])[lane];
        acc.x += p.x; acc.y += p.y; acc.z += p.z; acc.w += p.w;
        reinterpret_cast<float4*>(out + (size_t)b * TAHE_D)[lane] = acc;
    }
}

extern "C" void kernel_launch(void* const* d_in, const int* in_sizes, int n_in,
                              void* d_out, int out_size) {
    const float* rec = (const float*)d_in[0];
    const float* cur = (const float*)d_in[1];
    const int*   ts  = (const int*)  d_in[2];
    const float* emb = (const float*)d_in[3];
    float*       out = (float*)d_out;

    const int ctas = TAHE_B / ROWS_PER_CTA;  // 1024
    tahe_kernel<<<ctas, WARPS_PER_CTA * 32>>>(rec, cur, ts, emb, out);
}

// round 7
// speedup vs baseline: 1.2350x; 1.0175x over previous
#include <cuda_runtime.h>

// TAHE: masked cosine-similarity weighted pooling.
// out[b,d] = sum_l [ts[b,l]>0] * (dot(cur_n[b], rec_n[b,l]) + 1)/2 * emb[b,l,d]
//
// R6: (redux.f32 unsupported on sm_103 -> shuffle butterflies kept)
//     4 active rows per iteration with 8 front-batched LDG.128 (MLP x2 vs R3)
//     and 8-wide interleaved shuffle reduction per level.
//     Structure: 2 warps per batch row, compacted active-index list in smem.

#define TAHE_B 4096
#define TAHE_L 200
#define TAHE_D 128
#define WARPS_PER_CTA 8
#define ROWS_PER_CTA  4        // batch rows per CTA (2 warps each)
#define L_HALF        100      // L per warp

__global__ __launch_bounds__(WARPS_PER_CTA * 32)
void tahe_kernel(const float* __restrict__ rec,
                 const float* __restrict__ cur,
                 const int*   __restrict__ ts,
                 const float* __restrict__ emb,
                 float*       __restrict__ out) {
    __shared__ short s_list[WARPS_PER_CTA][L_HALF + 8];
    __shared__ float s_part[ROWS_PER_CTA][TAHE_D];   // partials from half==1 warps

    const int warp = threadIdx.x >> 5;
    const int lane = threadIdx.x & 31;
    const int row  = warp >> 1;              // 0..3 within CTA
    const int half = warp & 1;               // which L half
    const int b    = blockIdx.x * ROWS_PER_CTA + row;

    const unsigned lanemask_lt = (1u << lane) - 1u;

    // ---- normalize current representation (lane owns 4 contiguous floats) ----
    float4 c = reinterpret_cast<const float4*>(cur + (size_t)b * TAHE_D)[lane];
    float csq = c.x * c.x + c.y * c.y + c.z * c.z + c.w * c.w;
    #pragma unroll
    for (int o = 16; o > 0; o >>= 1)
        csq += __shfl_xor_sync(0xFFFFFFFFu, csq, o);
    const float cinv = rsqrtf(fmaxf(csq, 1e-12f));
    c.x *= cinv; c.y *= cinv; c.z *= cinv; c.w *= cinv;

    // ---- compact active l indices for this warp's L-half into smem ----
    const int* tsb = ts + (size_t)b * TAHE_L + half * L_HALF;
    int cnt = 0;
    #pragma unroll
    for (int chunk = 0; chunk < 4; chunk++) {           // 4*32 = 128 >= 100
        const int li = chunk * 32 + lane;
        const int t  = (li < L_HALF) ? tsb[li] : 0;
        const unsigned ballot = __ballot_sync(0xFFFFFFFFu, t > 0);
        if (t > 0)
            s_list[warp][cnt + __popc(ballot & lanemask_lt)] =
                (short)(half * L_HALF + li);
        cnt += __popc(ballot);
    }
    __syncwarp();

    const float4* recb = reinterpret_cast<const float4*>(rec + (size_t)b * TAHE_L * TAHE_D);
    const float4* embb = reinterpret_cast<const float4*>(emb + (size_t)b * TAHE_L * TAHE_D);

    float4 acc = make_float4(0.f, 0.f, 0.f, 0.f);

    // ---- main loop: 4 active rows/iter, 8 front-batched loads, 8-wide ILP ----
    int i = 0;
    for (; i + 4 <= cnt; i += 4) {
        const int l0 = s_list[warp][i];
        const int l1 = s_list[warp][i + 1];
        const int l2 = s_list[warp][i + 2];
        const int l3 = s_list[warp][i + 3];

        const float4 r0 = recb[(size_t)l0 * 32 + lane];
        const float4 r1 = recb[(size_t)l1 * 32 + lane];
        const float4 r2 = recb[(size_t)l2 * 32 + lane];
        const float4 r3 = recb[(size_t)l3 * 32 + lane];
        const float4 e0 = embb[(size_t)l0 * 32 + lane];
        const float4 e1 = embb[(size_t)l1 * 32 + lane];
        const float4 e2 = embb[(size_t)l2 * 32 + lane];
        const float4 e3 = embb[(size_t)l3 * 32 + lane];

        float d0 = r0.x*c.x + r0.y*c.y + r0.z*c.z + r0.w*c.w;
        float s0 = r0.x*r0.x + r0.y*r0.y + r0.z*r0.z + r0.w*r0.w;
        float d1 = r1.x*c.x + r1.y*c.y + r1.z*c.z + r1.w*c.w;
        float s1 = r1.x*r1.x + r1.y*r1.y + r1.z*r1.z + r1.w*r1.w;
        float d2 = r2.x*c.x + r2.y*c.y + r2.z*c.z + r2.w*c.w;
        float s2 = r2.x*r2.x + r2.y*r2.y + r2.z*r2.z + r2.w*r2.w;
        float d3 = r3.x*c.x + r3.y*c.y + r3.z*c.z + r3.w*c.w;
        float s3 = r3.x*r3.x + r3.y*r3.y + r3.z*r3.z + r3.w*r3.w;

        #pragma unroll
        for (int o = 16; o > 0; o >>= 1) {
            d0 += __shfl_xor_sync(0xFFFFFFFFu, d0, o);
            s0 += __shfl_xor_sync(0xFFFFFFFFu, s0, o);
            d1 += __shfl_xor_sync(0xFFFFFFFFu, d1, o);
            s1 += __shfl_xor_sync(0xFFFFFFFFu, s1, o);
            d2 += __shfl_xor_sync(0xFFFFFFFFu, d2, o);
            s2 += __shfl_xor_sync(0xFFFFFFFFu, s2, o);
            d3 += __shfl_xor_sync(0xFFFFFFFFu, d3, o);
            s3 += __shfl_xor_sync(0xFFFFFFFFu, s3, o);
        }

        const float w0 = (d0 * rsqrtf(fmaxf(s0, 1e-12f)) + 1.0f) * 0.5f;
        const float w1 = (d1 * rsqrtf(fmaxf(s1, 1e-12f)) + 1.0f) * 0.5f;
        const float w2 = (d2 * rsqrtf(fmaxf(s2, 1e-12f)) + 1.0f) * 0.5f;
        const float w3 = (d3 * rsqrtf(fmaxf(s3, 1e-12f)) + 1.0f) * 0.5f;

        acc.x = fmaf(w0, e0.x, fmaf(w1, e1.x, fmaf(w2, e2.x, fmaf(w3, e3.x, acc.x))));
        acc.y = fmaf(w0, e0.y, fmaf(w1, e1.y, fmaf(w2, e2.y, fmaf(w3, e3.y, acc.y))));
        acc.z = fmaf(w0, e0.z, fmaf(w1, e1.z, fmaf(w2, e2.z, fmaf(w3, e3.z, acc.z))));
        acc.w = fmaf(w0, e0.w, fmaf(w1, e1.w, fmaf(w2, e2.w, fmaf(w3, e3.w, acc.w))));
    }
    // ---- tail (0-3 rows) ----
    for (; i < cnt; i++) {
        const int la = s_list[warp][i];
        const float4 r0 = recb[(size_t)la * 32 + lane];
        const float4 e0 = embb[(size_t)la * 32 + lane];
        float d0 = r0.x*c.x + r0.y*c.y + r0.z*c.z + r0.w*c.w;
        float s0 = r0.x*r0.x + r0.y*r0.y + r0.z*r0.z + r0.w*r0.w;
        #pragma unroll
        for (int o = 16; o > 0; o >>= 1) {
            d0 += __shfl_xor_sync(0xFFFFFFFFu, d0, o);
            s0 += __shfl_xor_sync(0xFFFFFFFFu, s0, o);
        }
        const float w0 = (d0 * rsqrtf(fmaxf(s0, 1e-12f)) + 1.0f) * 0.5f;
        acc.x = fmaf(w0, e0.x, acc.x);
        acc.y = fmaf(w0, e0.y, acc.y);
        acc.z = fmaf(w0, e0.z, acc.z);
        acc.w = fmaf(w0, e0.w, acc.w);
    }

    // ---- combine the two half-warps ----
    if (half == 1)
        reinterpret_cast<float4*>(s_part[row])[lane] = acc;
    __syncthreads();
    if (half == 0) {
        const float4 p = reinterpret_cast<const float4*>(s_part[row])[lane];
        acc.x += p.x; acc.y += p.y; acc.z += p.z; acc.w += p.w;
        reinterpret_cast<float4*>(out + (size_t)b * TAHE_D)[lane] = acc;
    }
}

extern "C" void kernel_launch(void* const* d_in, const int* in_sizes, int n_in,
                              void* d_out, int out_size) {
    const float* rec = (const float*)d_in[0];
    const float* cur = (const float*)d_in[1];
    const int*   ts  = (const int*)  d_in[2];
    const float* emb = (const float*)d_in[3];
    float*       out = (float*)d_out;

    const int ctas = TAHE_B / ROWS_PER_CTA;  // 1024
    tahe_kernel<<<ctas, WARPS_PER_CTA * 32>>>(rec, cur, ts, emb, out);
}